// round 2
// baseline (speedup 1.0000x reference)
#include <cuda_runtime.h>

#define NN 100000
#define EE 1600000
#define BB 64
#define BNEPS 1e-5f

// ---------------- scratch (no allocs allowed) ----------------
__device__ __align__(16) float g_b0[(size_t)NN * 64];
__device__ __align__(16) float g_b1[(size_t)NN * 64];
__device__ __align__(16) float g_b2[(size_t)NN * 64];
__device__ int g_rows[EE];
__device__ int g_cols[EE];
__device__ int g_batch[NN];
__device__ float g_deg[NN];
__device__ float g_dis[NN];
__device__ float g_stats[128];          // [0:64) sum, [64:128) sumsq
__device__ __align__(16) float g_pool[BB * 64];
__device__ float g_cnt[BB];
__device__ int g_is64_e;
__device__ int g_is64_b;

// ---------------- dtype detection + index decode ----------------
__global__ void detect_dtype_kernel(const void* ei, const void* batch) {
    if (threadIdx.x != 0 || blockIdx.x != 0) return;
    // edge_index: if truly int64, first 64 entries (as int64) are all in [0, NN)
    const long long* p = (const long long*)ei;
    int ok = 1;
    for (int i = 0; i < 64; i++) {
        long long v = p[i];
        if (v < 0 || v >= NN) ok = 0;
    }
    g_is64_e = ok;
    // batch: probe mid-buffer (sorted, mid values ~BB/2, nonzero). Stay in the
    // first half so int32-sized buffer is never over-read.
    const long long* q = (const long long*)batch;
    int okb = 1;
    for (int i = 0; i < 32; i++) {
        long long v = q[NN / 4 + i];
        if (v < 0 || v >= BB) okb = 0;
    }
    g_is64_b = okb;
}

__global__ void decode_edges_kernel(const void* ei) {
    int e = blockIdx.x * blockDim.x + threadIdx.x;
    if (e >= EE) return;
    if (g_is64_e) {
        const long long* p = (const long long*)ei;
        g_rows[e] = (int)p[e];
        g_cols[e] = (int)p[EE + e];
    } else {
        const int* p = (const int*)ei;
        g_rows[e] = p[e];
        g_cols[e] = p[EE + e];
    }
}

__global__ void decode_batch_kernel(const void* batch) {
    int i = blockIdx.x * blockDim.x + threadIdx.x;
    if (i >= NN) return;
    if (g_is64_b) {
        const long long* p = (const long long*)batch;
        g_batch[i] = (int)p[i];
    } else {
        const int* p = (const int*)batch;
        g_batch[i] = p[i];
    }
}

// ---------------- degree / norm ----------------
__global__ void init_deg_kernel() {
    int i = blockIdx.x * blockDim.x + threadIdx.x;
    if (i < NN) g_deg[i] = 1.0f;  // self-loop
}

__global__ void count_deg_kernel() {
    int e = blockIdx.x * blockDim.x + threadIdx.x;
    if (e < EE) atomicAdd(&g_deg[g_cols[e]], 1.0f);
}

__global__ void make_dis_kernel() {
    int i = blockIdx.x * blockDim.x + threadIdx.x;
    if (i < NN) g_dis[i] = rsqrtf(g_deg[i]);
}

// ---------------- per-layer kernels ----------------
__global__ void zero_stats_kernel() {
    int t = threadIdx.x;
    if (t < 128) g_stats[t] = 0.0f;
}

// S[i][j] = A[i][j] = (H[i,:] @ W[:,j]) * dis[i]
__global__ void linear_scale_kernel(const float* __restrict__ H, const float* __restrict__ W,
                                    float* __restrict__ S, float* __restrict__ A,
                                    int din, int dout, int ld) {
    extern __shared__ float Wsh[];
    for (int i = threadIdx.x; i < din * dout; i += blockDim.x) Wsh[i] = W[i];
    __syncthreads();
    size_t total = (size_t)NN * dout;
    for (size_t idx = (size_t)blockIdx.x * blockDim.x + threadIdx.x; idx < total;
         idx += (size_t)gridDim.x * blockDim.x) {
        int i = (int)(idx >> ld);
        int j = (int)(idx & (dout - 1));
        const float* h = H + (size_t)i * din;
        float s = 0.0f;
        for (int k = 0; k < din; k++) s += h[k] * Wsh[k * dout + j];
        float v = s * g_dis[i];
        S[idx] = v;
        A[idx] = v;
    }
}

// A[col] += S[row] over all edges, 4 channels per thread via vector RED
__global__ void scatter_add_kernel(const float4* __restrict__ S4, float* __restrict__ A,
                                   int q, int lq) {
    long long idx = (long long)blockIdx.x * blockDim.x + threadIdx.x;
    long long total = (long long)EE * q;
    if (idx >= total) return;
    int e = (int)(idx >> lq);
    int c = (int)(idx & (q - 1));
    int r  = g_rows[e];
    int co = g_cols[e];
    float4 v = S4[(size_t)r * q + c];
    float* dst = A + ((size_t)co * q + c) * 4;
    unsigned long long p = (unsigned long long)__cvta_generic_to_global(dst);
    asm volatile("red.global.add.v4.f32 [%0], {%1,%2,%3,%4};"
                 :: "l"(p), "f"(v.x), "f"(v.y), "f"(v.z), "f"(v.w) : "memory");
}

// Y = A*dis + b ; accumulate per-channel sum/sumsq into g_stats
__global__ void bias_stats_kernel(const float* __restrict__ A, const float* __restrict__ bias,
                                  float* __restrict__ Y, int dout, int ld) {
    __shared__ float sh[256];
    __shared__ float sh2[256];
    int t = threadIdx.x;
    int c = t & (dout - 1);
    int rpb = 256 >> ld;
    int rstart = blockIdx.x * rpb + (t >> ld);
    int rstride = gridDim.x * rpb;
    float bc = bias[c];
    float s = 0.0f, s2 = 0.0f;
    for (int i = rstart; i < NN; i += rstride) {
        size_t off = (size_t)i * dout + c;
        float y = A[off] * g_dis[i] + bc;
        Y[off] = y;
        s += y;
        s2 += y * y;
    }
    sh[t] = s; sh2[t] = s2;
    __syncthreads();
    for (int off = 128; off >= dout; off >>= 1) {
        if (t < off) { sh[t] += sh[t + off]; sh2[t] += sh2[t + off]; }
        __syncthreads();
    }
    if (t < dout) {
        atomicAdd(&g_stats[c], sh[t]);
        atomicAdd(&g_stats[64 + c], sh2[t]);
    }
}

// Y = relu(bn(Y)) in place
__global__ void bn_apply_kernel(float* __restrict__ Y, const float* __restrict__ g,
                                const float* __restrict__ be, int dout, int ld) {
    size_t idx = (size_t)blockIdx.x * blockDim.x + threadIdx.x;
    size_t total = (size_t)NN * dout;
    if (idx >= total) return;
    int c = (int)(idx & (dout - 1));
    float mean = g_stats[c] * (1.0f / NN);
    float var  = g_stats[64 + c] * (1.0f / NN) - mean * mean;
    float inv  = rsqrtf(var + BNEPS);
    float a  = g[c] * inv;
    float sh = be[c] - mean * a;
    float y = Y[idx] * a + sh;
    Y[idx] = fmaxf(y, 0.0f);
}

// ---------------- pooling + FC ----------------
__global__ void zero_pool_kernel() {
    int t = blockIdx.x * blockDim.x + threadIdx.x;
    if (t < BB * 64) g_pool[t] = 0.0f;
    if (t < BB) g_cnt[t] = 0.0f;
}

__global__ void pool_kernel(const float4* __restrict__ H4) {
    int idx = blockIdx.x * blockDim.x + threadIdx.x;
    if (idx >= NN * 16) return;
    int i = idx >> 4;
    int c = idx & 15;
    int b = g_batch[i];
    float4 v = H4[(size_t)i * 16 + c];
    float* dst = g_pool + ((size_t)b * 16 + c) * 4;
    unsigned long long p = (unsigned long long)__cvta_generic_to_global(dst);
    asm volatile("red.global.add.v4.f32 [%0], {%1,%2,%3,%4};"
                 :: "l"(p), "f"(v.x), "f"(v.y), "f"(v.z), "f"(v.w) : "memory");
    if (c == 0) atomicAdd(&g_cnt[b], 1.0f);
}

__global__ void fc_kernel(const float* __restrict__ fcW, const float* __restrict__ fcb,
                          float* __restrict__ out) {
    int t = blockIdx.x * blockDim.x + threadIdx.x;
    if (t >= BB * 10) return;
    int b = t / 10;
    int k = t % 10;
    float cnt = fmaxf(g_cnt[b], 1.0f);
    float s = 0.0f;
    for (int j = 0; j < 64; j++) s += g_pool[b * 64 + j] * fcW[j * 10 + k];
    out[t] = s / cnt + fcb[k];
}

// ---------------- host orchestration ----------------
static void run_layer(const float* H, const float* W, const float* bias,
                      const float* g, const float* be,
                      float* S, float* A, int din, int dout, int ld) {
    zero_stats_kernel<<<1, 128>>>();
    size_t total = (size_t)NN * dout;
    int blocks = (int)((total + 255) / 256);
    int lsblocks = blocks > 4096 ? 4096 : blocks;
    linear_scale_kernel<<<lsblocks, 256, din * dout * sizeof(float)>>>(H, W, S, A, din, dout, ld);
    int q = dout / 4, lq = ld - 2;
    long long stot = (long long)EE * q;
    scatter_add_kernel<<<(int)((stot + 255) / 256), 256>>>((const float4*)S, A, q, lq);
    bias_stats_kernel<<<1024, 256>>>(A, bias, S, dout, ld);
    bn_apply_kernel<<<blocks, 256>>>(S, g, be, dout, ld);
}

extern "C" void kernel_launch(void* const* d_in, const int* in_sizes, int n_in,
                              void* d_out, int out_size) {
    const float* x     = (const float*)d_in[0];
    const void*  ei    = d_in[1];
    const void*  batch = d_in[2];
    const float* W1 = (const float*)d_in[3];
    const float* b1 = (const float*)d_in[4];
    const float* g1 = (const float*)d_in[5];
    const float* be1 = (const float*)d_in[6];
    const float* W2 = (const float*)d_in[7];
    const float* b2 = (const float*)d_in[8];
    const float* g2 = (const float*)d_in[9];
    const float* be2 = (const float*)d_in[10];
    const float* W3 = (const float*)d_in[11];
    const float* b3 = (const float*)d_in[12];
    const float* g3 = (const float*)d_in[13];
    const float* be3 = (const float*)d_in[14];
    const float* fcW = (const float*)d_in[15];
    const float* fcb = (const float*)d_in[16];
    float* out = (float*)d_out;

    float *b0p, *b1p, *b2p;
    cudaGetSymbolAddress((void**)&b0p, g_b0);
    cudaGetSymbolAddress((void**)&b1p, g_b1);
    cudaGetSymbolAddress((void**)&b2p, g_b2);

    // dtype detection + index decode (int64 vs int32)
    detect_dtype_kernel<<<1, 32>>>(ei, batch);
    decode_edges_kernel<<<(EE + 255) / 256, 256>>>(ei);
    decode_batch_kernel<<<(NN + 255) / 256, 256>>>(batch);

    // degree + rsqrt
    init_deg_kernel<<<(NN + 255) / 256, 256>>>();
    count_deg_kernel<<<(EE + 255) / 256, 256>>>();
    make_dis_kernel<<<(NN + 255) / 256, 256>>>();

    // layer 1: in=x(3), out=16  -> h1 in b0
    run_layer(x,   W1, b1, g1, be1, b0p, b1p, 3, 16, 4);
    // layer 2: in=b0(16), out=32 -> h2 in b1
    run_layer(b0p, W2, b2, g2, be2, b1p, b2p, 16, 32, 5);
    // layer 3: in=b1(32), out=64 -> h3 in b2
    run_layer(b1p, W3, b3, g3, be3, b2p, b0p, 32, 64, 6);

    // pooling + FC
    zero_pool_kernel<<<(BB * 64 + 255) / 256, 256>>>();
    pool_kernel<<<(NN * 16 + 255) / 256, 256>>>((const float4*)b2p);
    fc_kernel<<<(BB * 10 + 255) / 256, 256>>>(fcW, fcb, out);
}

// round 3
// speedup vs baseline: 1.6321x; 1.6321x over previous
#include <cuda_runtime.h>

#define NN 100000
#define EE 1600000
#define BB 64
#define BNEPS 1e-5f

// ---------------- scratch ----------------
__device__ __align__(16) float g_P[(size_t)NN * 32];   // pre-scaled scatter source
__device__ __align__(16) float g_A[(size_t)NN * 32];   // aggregation buffer
__device__ __align__(16) float g_Y[(size_t)NN * 64];   // layer output
__device__ __align__(16) int2 g_edge[EE];
__device__ int g_batch[NN];
__device__ float g_deg[NN];
__device__ float g_dis[NN];
__device__ float g_stats[128];
__device__ __align__(16) float g_pool[BB * 64];
__device__ float g_cnt[BB];
__device__ int g_is64_e;
__device__ int g_is64_b;

// ---------------- dtype detection ----------------
__global__ void detect_dtype_kernel(const void* ei, const void* batch) {
    if (threadIdx.x != 0 || blockIdx.x != 0) return;
    const long long* p = (const long long*)ei;
    int ok = 1;
    for (int i = 0; i < 64; i++) {
        long long v = p[i];
        if (v < 0 || v >= NN) ok = 0;
    }
    g_is64_e = ok;
    const long long* q = (const long long*)batch;
    int okb = 1;
    for (int i = 0; i < 32; i++) {
        long long v = q[NN / 4 + i];
        if (v < 0 || v >= BB) okb = 0;
    }
    g_is64_b = okb;
}

__global__ void init_deg_kernel() {
    int i = blockIdx.x * blockDim.x + threadIdx.x;
    if (i < NN) g_deg[i] = 1.0f;  // self-loop
}

// decode edges (int64 or int32) + degree histogram in one pass
__global__ void decode_edges_kernel(const void* ei) {
    int e = blockIdx.x * blockDim.x + threadIdx.x;
    if (e >= EE) return;
    int r, c;
    if (g_is64_e) {
        const long long* p = (const long long*)ei;
        r = (int)p[e]; c = (int)p[EE + e];
    } else {
        const int* p = (const int*)ei;
        r = p[e]; c = p[EE + e];
    }
    g_edge[e] = make_int2(r, c);
    atomicAdd(&g_deg[c], 1.0f);
}

__global__ void decode_batch_kernel(const void* batch) {
    int i = blockIdx.x * blockDim.x + threadIdx.x;
    if (i >= NN) return;
    g_batch[i] = g_is64_b ? (int)((const long long*)batch)[i]
                          : ((const int*)batch)[i];
}

__global__ void make_dis_kernel() {
    int i = blockIdx.x * blockDim.x + threadIdx.x;
    if (i < NN) g_dis[i] = rsqrtf(g_deg[i]);
}

// ---------------- layer 1 prep: P = A = [x*dis, 0-pad] ----------------
__global__ void prep1_kernel(const float* __restrict__ x) {
    int i = blockIdx.x * blockDim.x + threadIdx.x;
    if (i >= NN) return;
    float d = g_dis[i];
    float4 v = make_float4(x[3 * i] * d, x[3 * i + 1] * d, x[3 * i + 2] * d, 0.0f);
    ((float4*)g_P)[i] = v;
    ((float4*)g_A)[i] = v;
}

// ---------------- scatter: A[col] += P[row], float4 channels ----------------
__global__ void scatter_add_kernel(const float4* __restrict__ P4, float* __restrict__ A,
                                   int q, int lq) {
    long long idx = (long long)blockIdx.x * blockDim.x + threadIdx.x;
    long long total = (long long)EE * q;
    if (idx >= total) return;
    int e = (int)(idx >> lq);
    int c = (int)(idx & (q - 1));
    int2 rc = g_edge[e];
    float4 v = P4[(size_t)rc.x * q + c];
    float* dst = A + ((size_t)rc.y * q + c) * 4;
    unsigned long long p = (unsigned long long)__cvta_generic_to_global(dst);
    asm volatile("red.global.add.v4.f32 [%0], {%1,%2,%3,%4};"
                 :: "l"(p), "f"(v.x), "f"(v.y), "f"(v.z), "f"(v.w) : "memory");
}

__global__ void zero_stats_kernel() {
    int t = threadIdx.x;
    if (t < 128) g_stats[t] = 0.0f;
}

// ---------------- Y = (A @ W) * dis + b ; accumulate channel stats ----------------
__global__ void linear_stats_kernel(const float* __restrict__ A, const float* __restrict__ W,
                                    const float* __restrict__ bias, float* __restrict__ Y,
                                    int din, int astride, int dout, int ld) {
    extern __shared__ float Wsh[];
    for (int i = threadIdx.x; i < din * dout; i += blockDim.x) Wsh[i] = W[i];
    __syncthreads();
    __shared__ float sh[256];
    __shared__ float sh2[256];
    int t = threadIdx.x;
    int c = t & (dout - 1);
    int rpb = 256 >> ld;
    int rstart = blockIdx.x * rpb + (t >> ld);
    int rstride = gridDim.x * rpb;
    float bc = bias[c];
    float s = 0.0f, s2 = 0.0f;
    for (int i = rstart; i < NN; i += rstride) {
        const float* a = A + (size_t)i * astride;
        float dot = 0.0f;
        for (int k = 0; k < din; k++) dot += a[k] * Wsh[k * dout + c];
        float y = dot * g_dis[i] + bc;
        Y[(size_t)i * dout + c] = y;
        s += y; s2 += y * y;
    }
    sh[t] = s; sh2[t] = s2;
    __syncthreads();
    for (int off = 128; off >= dout; off >>= 1) {
        if (t < off) { sh[t] += sh[t + off]; sh2[t] += sh2[t + off]; }
        __syncthreads();
    }
    if (t < dout) {
        atomicAdd(&g_stats[c], sh[t]);
        atomicAdd(&g_stats[64 + c], sh2[t]);
    }
}

// ---------------- bn+relu; optionally emit next layer's P and A (=h*dis) ----------------
__global__ void bn_next_kernel(float* __restrict__ Y, const float* __restrict__ g,
                               const float* __restrict__ be, int dout, int ld,
                               float* __restrict__ Pout, float* __restrict__ Aout,
                               int write_scaled) {
    size_t idx = (size_t)blockIdx.x * blockDim.x + threadIdx.x;
    size_t total = (size_t)NN * dout;
    if (idx >= total) return;
    int c = (int)(idx & (dout - 1));
    int i = (int)(idx >> ld);
    float mean = g_stats[c] * (1.0f / NN);
    float var  = g_stats[64 + c] * (1.0f / NN) - mean * mean;
    float inv  = rsqrtf(var + BNEPS);
    float a  = g[c] * inv;
    float shv = be[c] - mean * a;
    float h = fmaxf(Y[idx] * a + shv, 0.0f);
    if (write_scaled) {
        float v = h * g_dis[i];
        Pout[idx] = v;
        Aout[idx] = v;
    } else {
        Y[idx] = h;
    }
}

// ---------------- pooling + FC ----------------
__global__ void zero_pool_kernel() {
    int t = blockIdx.x * blockDim.x + threadIdx.x;
    if (t < BB * 64) g_pool[t] = 0.0f;
    if (t < BB) g_cnt[t] = 0.0f;
}

__global__ void pool_kernel(const float4* __restrict__ H4) {
    int idx = blockIdx.x * blockDim.x + threadIdx.x;
    if (idx >= NN * 16) return;
    int i = idx >> 4;
    int c = idx & 15;
    int b = g_batch[i];
    float4 v = H4[(size_t)i * 16 + c];
    float* dst = g_pool + ((size_t)b * 16 + c) * 4;
    unsigned long long p = (unsigned long long)__cvta_generic_to_global(dst);
    asm volatile("red.global.add.v4.f32 [%0], {%1,%2,%3,%4};"
                 :: "l"(p), "f"(v.x), "f"(v.y), "f"(v.z), "f"(v.w) : "memory");
    if (c == 0) atomicAdd(&g_cnt[b], 1.0f);
}

__global__ void fc_kernel(const float* __restrict__ fcW, const float* __restrict__ fcb,
                          float* __restrict__ out) {
    int t = blockIdx.x * blockDim.x + threadIdx.x;
    if (t >= BB * 10) return;
    int b = t / 10;
    int k = t % 10;
    float cnt = fmaxf(g_cnt[b], 1.0f);
    float s = 0.0f;
    for (int j = 0; j < 64; j++) s += g_pool[b * 64 + j] * fcW[j * 10 + k];
    out[t] = s / cnt + fcb[k];
}

extern "C" void kernel_launch(void* const* d_in, const int* in_sizes, int n_in,
                              void* d_out, int out_size) {
    const float* x     = (const float*)d_in[0];
    const void*  ei    = d_in[1];
    const void*  batch = d_in[2];
    const float* W1 = (const float*)d_in[3];
    const float* b1 = (const float*)d_in[4];
    const float* g1 = (const float*)d_in[5];
    const float* be1 = (const float*)d_in[6];
    const float* W2 = (const float*)d_in[7];
    const float* b2 = (const float*)d_in[8];
    const float* g2 = (const float*)d_in[9];
    const float* be2 = (const float*)d_in[10];
    const float* W3 = (const float*)d_in[11];
    const float* b3 = (const float*)d_in[12];
    const float* g3 = (const float*)d_in[13];
    const float* be3 = (const float*)d_in[14];
    const float* fcW = (const float*)d_in[15];
    const float* fcb = (const float*)d_in[16];
    float* out = (float*)d_out;

    float *Pp, *Ap, *Yp;
    cudaGetSymbolAddress((void**)&Pp, g_P);
    cudaGetSymbolAddress((void**)&Ap, g_A);
    cudaGetSymbolAddress((void**)&Yp, g_Y);

    // decode + degree + norm
    init_deg_kernel<<<(NN + 255) / 256, 256>>>();
    detect_dtype_kernel<<<1, 32>>>(ei, batch);
    decode_edges_kernel<<<(EE + 255) / 256, 256>>>(ei);
    decode_batch_kernel<<<(NN + 255) / 256, 256>>>(batch);
    make_dis_kernel<<<(NN + 255) / 256, 256>>>();

    // ---- layer 1: scatter on 4 padded channels, then @W1 (3->16) ----
    prep1_kernel<<<(NN + 255) / 256, 256>>>(x);
    scatter_add_kernel<<<(EE + 255) / 256, 256>>>((const float4*)Pp, Ap, 1, 0);
    zero_stats_kernel<<<1, 128>>>();
    linear_stats_kernel<<<1024, 256, 3 * 16 * sizeof(float)>>>(Ap, W1, b1, Yp, 3, 4, 16, 4);
    bn_next_kernel<<<(NN * 16 + 255) / 256, 256>>>(Yp, g1, be1, 16, 4, Pp, Ap, 1);

    // ---- layer 2: scatter on 16 channels, then @W2 (16->32) ----
    {
        long long tot = (long long)EE * 4;
        scatter_add_kernel<<<(int)((tot + 255) / 256), 256>>>((const float4*)Pp, Ap, 4, 2);
    }
    zero_stats_kernel<<<1, 128>>>();
    linear_stats_kernel<<<1024, 256, 16 * 32 * sizeof(float)>>>(Ap, W2, b2, Yp, 16, 16, 32, 5);
    bn_next_kernel<<<(NN * 32 + 255) / 256, 256>>>(Yp, g2, be2, 32, 5, Pp, Ap, 1);

    // ---- layer 3: scatter on 32 channels, then @W3 (32->64) ----
    {
        long long tot = (long long)EE * 8;
        scatter_add_kernel<<<(int)((tot + 255) / 256), 256>>>((const float4*)Pp, Ap, 8, 3);
    }
    zero_stats_kernel<<<1, 128>>>();
    linear_stats_kernel<<<1024, 256, 32 * 64 * sizeof(float)>>>(Ap, W3, b3, Yp, 32, 32, 64, 6);
    bn_next_kernel<<<(NN * 64 + 255) / 256, 256>>>(Yp, g3, be3, 64, 6, Pp, Ap, 0);

    // ---- pooling + FC ----
    zero_pool_kernel<<<(BB * 64 + 255) / 256, 256>>>();
    pool_kernel<<<(NN * 16 + 255) / 256, 256>>>((const float4*)Yp);
    fc_kernel<<<(BB * 10 + 255) / 256, 256>>>(fcW, fcb, out);
}